// round 4
// baseline (speedup 1.0000x reference)
#include <cuda_runtime.h>
#include <cstdint>

#define HDIM  512
#define KNBR  32
#define NHEADS 8
#define NBINS 10
#define NMAX  10000
#define NEG_SLOPE 0.2f
#define PROJW 1536   // [S | Pn | Wt]

__device__ float g_bpack[PROJW * HDIM];                 // packed weights, row j contiguous over h
__device__ float g_proj[(size_t)NMAX * PROJW];          // per-node projections

__device__ __forceinline__ float lrelu(float x) {
    return x >= 0.0f ? x : NEG_SLOPE * x;
}

// ---------------------------------------------------------------------------
// Pack [P_self; P_nbr; W_w] into one 1536x512 row-major (over h) matrix.
// ---------------------------------------------------------------------------
__global__ void pack_kernel(const float* __restrict__ P_w, const float* __restrict__ W_w) {
    int idx = blockIdx.x * blockDim.x + threadIdx.x;
    if (idx >= PROJW * HDIM) return;
    int j = idx >> 9;        // output row (d within one of 3 mats)
    int h = idx & (HDIM - 1);
    float v;
    if (j < 512)        v = P_w[(size_t)j * 1024 + h];              // P_self[d,h]
    else if (j < 1024)  v = P_w[(size_t)(j - 512) * 1024 + 512 + h];// P_nbr[d,h]
    else                v = W_w[(size_t)(j - 1024) * 512 + h];      // W_w[d,h]
    g_bpack[idx] = v;
}

// ---------------------------------------------------------------------------
// SGEMM (NT): C[m, j] = sum_h A[m,h] * B[j,h].  A = z (M x 512), B = g_bpack
// (1536 x 512), C = g_proj (M x 1536).  128x128x8 tiles, 256 thr, 8x8/thread.
// ---------------------------------------------------------------------------
#define BM 128
#define BN 128
#define BK 8

__global__ __launch_bounds__(256) void sgemm_kernel(const float* __restrict__ A, int M) {
    __shared__ float As[BK][BM];
    __shared__ float Bs[BK][BN];

    const float* B = g_bpack;
    float* C = g_proj;

    const int bn  = blockIdx.x * BN;
    const int bm  = blockIdx.y * BM;
    const int tid = threadIdx.x;
    const int tr  = tid >> 4;     // 0..15
    const int tc  = tid & 15;     // 0..15

    const int lrow = tid >> 1;          // 0..127
    const int lk   = (tid & 1) * 4;     // 0 or 4

    float acc[8][8];
#pragma unroll
    for (int i = 0; i < 8; i++)
#pragma unroll
        for (int j = 0; j < 8; j++) acc[i][j] = 0.0f;

    const bool arow_ok = (bm + lrow) < M;
    const float* Aptr = A + (size_t)(bm + lrow) * HDIM + lk;
    const float* Bptr = B + (size_t)(bn + lrow) * HDIM + lk;

    for (int k0 = 0; k0 < HDIM; k0 += BK) {
        float4 av = arow_ok ? *(const float4*)(Aptr + k0) : make_float4(0.f, 0.f, 0.f, 0.f);
        float4 bv = *(const float4*)(Bptr + k0);
        As[lk + 0][lrow] = av.x; As[lk + 1][lrow] = av.y;
        As[lk + 2][lrow] = av.z; As[lk + 3][lrow] = av.w;
        Bs[lk + 0][lrow] = bv.x; Bs[lk + 1][lrow] = bv.y;
        Bs[lk + 2][lrow] = bv.z; Bs[lk + 3][lrow] = bv.w;
        __syncthreads();

#pragma unroll
        for (int kk = 0; kk < BK; kk++) {
            float a[8], b[8];
            *(float4*)&a[0] = *(const float4*)&As[kk][tr * 8];
            *(float4*)&a[4] = *(const float4*)&As[kk][tr * 8 + 4];
            *(float4*)&b[0] = *(const float4*)&Bs[kk][tc * 8];
            *(float4*)&b[4] = *(const float4*)&Bs[kk][tc * 8 + 4];
#pragma unroll
            for (int i = 0; i < 8; i++)
#pragma unroll
                for (int j = 0; j < 8; j++) acc[i][j] += a[i] * b[j];
        }
        __syncthreads();
    }

#pragma unroll
    for (int i = 0; i < 8; i++) {
        int row = bm + tr * 8 + i;
        if (row < M) {
            float* crow = C + (size_t)row * PROJW + bn + tc * 8;
            *(float4*)(crow)     = *(float4*)&acc[i][0];
            *(float4*)(crow + 4) = *(float4*)&acc[i][4];
        }
    }
}

// ---------------------------------------------------------------------------
// Edge phase: scores + softmax + aggregate + residual, NPB nodes per block.
// NOTE: neighbor_indices / affinity_bins are int32 on device (JAX x64 is off).
// ---------------------------------------------------------------------------
#define NPB 4

__global__ __launch_bounds__(256) void edge_kernel(
    const float* __restrict__ z, const int* __restrict__ nbr,
    const int* __restrict__ bins, const float* __restrict__ y_w,
    const float* __restrict__ c_bins, const float* __restrict__ rw,
    float* __restrict__ out, int N)
{
    __shared__ float s_y[NHEADS * HDIM];      // 16 KB
    __shared__ float s_S[HDIM];               // 2 KB
    __shared__ float s_sc[KNBR * NHEADS];     // scores -> attn
    __shared__ int   s_idx[KNBR];
    __shared__ int   s_bin[KNBR];
    __shared__ float s_cb[NBINS * NHEADS];
    __shared__ int   s_anyvalid;

    const int tid  = threadIdx.x;
    const int lane = tid & 31;
    const int warp = tid >> 5;

    for (int i = tid; i < NHEADS * HDIM; i += 256) s_y[i] = y_w[i];
    if (tid < NBINS * NHEADS) s_cb[tid] = c_bins[tid];
    const float rweight = rw[0];

    for (int ni = 0; ni < NPB; ni++) {
        const int node = blockIdx.x * NPB + ni;
        if (node >= N) break;   // uniform across block

        __syncthreads();        // guards smem reuse + initial y/cb loads
        s_S[tid]       = g_proj[(size_t)node * PROJW + tid];
        s_S[tid + 256] = g_proj[(size_t)node * PROJW + tid + 256];
        if (warp == 0) {
            int m = nbr[(size_t)node * KNBR + lane];
            s_idx[lane] = m;
            s_bin[lane] = bins[(size_t)node * KNBR + lane];
            unsigned bal = __ballot_sync(0xffffffffu, m >= 0);
            if (lane == 0) s_anyvalid = (bal != 0u);
        }
        __syncthreads();

        if (!s_anyvalid) {
            out[(size_t)node * HDIM + tid]       = z[(size_t)node * HDIM + tid];
            out[(size_t)node * HDIM + tid + 256] = z[(size_t)node * HDIM + tid + 256];
            continue;
        }

        // ---- scores: warp w handles k = w, w+8, ... ----
        const float4* s4 = (const float4*)s_S;
        const float4* y4 = (const float4*)s_y;
        for (int k = warp; k < KNBR; k += 8) {
            const int m = s_idx[k];
            float acc[NHEADS];
#pragma unroll
            for (int e = 0; e < NHEADS; e++) acc[e] = 0.0f;
            if (m >= 0) {
                const float4* prow = (const float4*)(g_proj + (size_t)m * PROJW + 512);
#pragma unroll
                for (int i = 0; i < 4; i++) {
                    const int dv = i * 32 + lane;
                    float4 p = prow[dv];
                    float4 s = s4[dv];
                    float h0 = lrelu(p.x + s.x);
                    float h1 = lrelu(p.y + s.y);
                    float h2 = lrelu(p.z + s.z);
                    float h3 = lrelu(p.w + s.w);
#pragma unroll
                    for (int e = 0; e < NHEADS; e++) {
                        float4 yv = y4[e * 128 + dv];
                        acc[e] += yv.x * h0 + yv.y * h1 + yv.z * h2 + yv.w * h3;
                    }
                }
            }
#pragma unroll
            for (int e = 0; e < NHEADS; e++) {
                float v = acc[e];
                v += __shfl_down_sync(0xffffffffu, v, 16);
                v += __shfl_down_sync(0xffffffffu, v, 8);
                v += __shfl_down_sync(0xffffffffu, v, 4);
                v += __shfl_down_sync(0xffffffffu, v, 2);
                v += __shfl_down_sync(0xffffffffu, v, 1);
                if (lane == 0)
                    s_sc[k * NHEADS + e] =
                        (m >= 0) ? (v + s_cb[s_bin[k] * NHEADS + e]) : -1.0e9f;
            }
        }
        __syncthreads();

        // ---- softmax over k, per head (8 threads) ----
        if (tid < NHEADS) {
            float mx = -3.0e38f;
#pragma unroll
            for (int k = 0; k < KNBR; k++) mx = fmaxf(mx, s_sc[k * NHEADS + tid]);
            float sum = 0.0f;
#pragma unroll
            for (int k = 0; k < KNBR; k++) sum += expf(s_sc[k * NHEADS + tid] - mx);
            float inv = 1.0f / sum;
#pragma unroll
            for (int k = 0; k < KNBR; k++)
                s_sc[k * NHEADS + tid] = expf(s_sc[k * NHEADS + tid] - mx) * inv;
        }
        __syncthreads();

        // ---- aggregate + residual: thread owns d = tid and tid+256 ----
        const int d0 = tid, d1 = tid + 256;
        const int e0 = d0 >> 6, e1 = d1 >> 6;
        float acc0 = 0.0f, acc1 = 0.0f;
#pragma unroll 4
        for (int k = 0; k < KNBR; k++) {
            const int m = s_idx[k];
            if (m < 0) continue;   // attn is exactly 0 for invalid edges
            const float* wrow = g_proj + (size_t)m * PROJW + 1024;
            acc0 += s_sc[k * NHEADS + e0] * wrow[d0];
            acc1 += s_sc[k * NHEADS + e1] * wrow[d1];
        }
        const float z0 = z[(size_t)node * HDIM + d0];
        const float z1 = z[(size_t)node * HDIM + d1];
        out[(size_t)node * HDIM + d0] = lrelu(acc0 + rweight * z0);
        out[(size_t)node * HDIM + d1] = lrelu(acc1 + rweight * z1);
    }
}

// ---------------------------------------------------------------------------
extern "C" void kernel_launch(void* const* d_in, const int* in_sizes, int n_in,
                              void* d_out, int out_size) {
    const float* z      = (const float*)d_in[0];
    // d_in[1] (A) is all zeros and unused by the reference — skipped.
    const int*   nbr    = (const int*)d_in[2];
    const int*   bins   = (const int*)d_in[3];
    const float* P_w    = (const float*)d_in[4];
    const float* y_w    = (const float*)d_in[5];
    const float* W_w    = (const float*)d_in[6];
    const float* c_bins = (const float*)d_in[7];
    const float* rw     = (const float*)d_in[8];
    float*       out    = (float*)d_out;

    const int N = in_sizes[0] / HDIM;

    pack_kernel<<<(PROJW * HDIM + 255) / 256, 256>>>(P_w, W_w);

    dim3 g(PROJW / BN, (N + BM - 1) / BM);
    sgemm_kernel<<<g, 256>>>(z, N);

    edge_kernel<<<(N + NPB - 1) / NPB, 256>>>(z, nbr, bins, y_w, c_bins, rw, out, N);
}

// round 7
// speedup vs baseline: 1.3354x; 1.3354x over previous
#include <cuda_runtime.h>
#include <cuda_bf16.h>
#include <mma.h>
#include <cstdint>

using namespace nvcuda;

#define HDIM  512
#define KNBR  32
#define NHEADS 8
#define NBINS 10
#define NMAX  10000
#define MPAD  10112      // ceil(10000/128)*128
#define NEG_SLOPE 0.2f
#define PROJW 1536       // [S | Pn | Wt]

__device__ float g_proj[(size_t)MPAD * PROJW];          // per-node projections (fp32)
__device__ __nv_bfloat16 g_Ahi[(size_t)MPAD * HDIM];
__device__ __nv_bfloat16 g_Alo[(size_t)MPAD * HDIM];
__device__ __nv_bfloat16 g_Bhi[(size_t)PROJW * HDIM];
__device__ __nv_bfloat16 g_Blo[(size_t)PROJW * HDIM];

__device__ __forceinline__ float lrelu(float x) {
    return x >= 0.0f ? x : NEG_SLOPE * x;
}

// ===========================================================================
// Conversions: fp32 -> (hi, lo) bf16 split
// ===========================================================================
__global__ void conv_a_kernel(const float* __restrict__ z, int M, int Mp) {
    int i = blockIdx.x * blockDim.x + threadIdx.x;
    if (i >= Mp * HDIM) return;
    int row = i >> 9;
    float x = (row < M) ? z[i] : 0.0f;
    __nv_bfloat16 h = __float2bfloat16(x);
    g_Ahi[i] = h;
    g_Alo[i] = __float2bfloat16(x - __bfloat162float(h));
}

__global__ void conv_b_kernel(const float* __restrict__ P_w, const float* __restrict__ W_w) {
    int i = blockIdx.x * blockDim.x + threadIdx.x;
    if (i >= PROJW * HDIM) return;
    int j = i >> 9;
    int hcol = i & (HDIM - 1);
    float x;
    if (j < 512)        x = P_w[(size_t)j * 1024 + hcol];
    else if (j < 1024)  x = P_w[(size_t)(j - 512) * 1024 + 512 + hcol];
    else                x = W_w[(size_t)(j - 1024) * 512 + hcol];
    __nv_bfloat16 h = __float2bfloat16(x);
    g_Bhi[i] = h;
    g_Blo[i] = __float2bfloat16(x - __bfloat162float(h));
}

// ===========================================================================
// wmma bf16 3-term GEMM: C[m,j] = sum_h A[m,h]*B[j,h]  (fp32 accumulate)
// CTA tile 128x128, 8 warps (4m x 2n), warp tile 32x64 (2x4 wmma frags).
// K chunked by 32: 4 smem tiles of 128 x 48(padded) bf16 = 48 KB.
// ===========================================================================
#define KC 32
#define LPAD 48   // padded row length in elements; 96 B row stride (16B-aligned)
#define TILE_ELEMS (128 * LPAD)
#define GEMM_SMEM (4 * TILE_ELEMS * 2)

__global__ __launch_bounds__(256) void gemm_wmma_kernel(int M) {
    extern __shared__ __nv_bfloat16 sm[];
    __nv_bfloat16* sAhi = sm;
    __nv_bfloat16* sAlo = sm + TILE_ELEMS;
    __nv_bfloat16* sBhi = sm + 2 * TILE_ELEMS;
    __nv_bfloat16* sBlo = sm + 3 * TILE_ELEMS;

    const int tid = threadIdx.x;
    const int wid = tid >> 5;
    const int bm = blockIdx.y * 128;
    const int bn = blockIdx.x * 128;
    const int wm = wid & 3;    // 0..3 -> m offset wm*32
    const int wn = wid >> 2;   // 0..1 -> n offset wn*64

    wmma::fragment<wmma::accumulator, 16, 16, 16, float> acc[2][4];
#pragma unroll
    for (int i = 0; i < 2; i++)
#pragma unroll
        for (int j = 0; j < 4; j++) wmma::fill_fragment(acc[i][j], 0.0f);

    const __nv_bfloat16* gsrc[4];
    gsrc[0] = g_Ahi + (size_t)bm * HDIM;
    gsrc[1] = g_Alo + (size_t)bm * HDIM;
    gsrc[2] = g_Bhi + (size_t)bn * HDIM;
    gsrc[3] = g_Blo + (size_t)bn * HDIM;
    __nv_bfloat16* sdst[4] = { sAhi, sAlo, sBhi, sBlo };

    for (int k0 = 0; k0 < HDIM; k0 += KC) {
        __syncthreads();   // protect previous iteration's reads
        // Each tile: 128 rows x 32 bf16 (64 B) = 512 uint4 vectors.
#pragma unroll
        for (int t = 0; t < 4; t++) {
            const __nv_bfloat16* src = gsrc[t] + k0;
            __nv_bfloat16* dst = sdst[t];
#pragma unroll
            for (int it = 0; it < 2; it++) {
                int v = tid + it * 256;       // 0..511
                int row = v >> 2;
                int c = v & 3;                // 8-element (16B) vector index
                uint4 val = *(const uint4*)(src + (size_t)row * HDIM + c * 8);
                *(uint4*)(dst + row * LPAD + c * 8) = val;
            }
        }
        __syncthreads();

#pragma unroll
        for (int ks = 0; ks < KC; ks += 16) {
            wmma::fragment<wmma::matrix_a, 16, 16, 16, __nv_bfloat16, wmma::row_major> a0, a1;
            wmma::fragment<wmma::matrix_b, 16, 16, 16, __nv_bfloat16, wmma::col_major> b[4];

            // term 1: hi * hi
            wmma::load_matrix_sync(a0, sAhi + (wm * 32 +  0) * LPAD + ks, LPAD);
            wmma::load_matrix_sync(a1, sAhi + (wm * 32 + 16) * LPAD + ks, LPAD);
#pragma unroll
            for (int ni = 0; ni < 4; ni++)
                wmma::load_matrix_sync(b[ni], sBhi + (wn * 64 + ni * 16) * LPAD + ks, LPAD);
#pragma unroll
            for (int ni = 0; ni < 4; ni++) {
                wmma::mma_sync(acc[0][ni], a0, b[ni], acc[0][ni]);
                wmma::mma_sync(acc[1][ni], a1, b[ni], acc[1][ni]);
            }
            // term 2: hi * lo  (a still hi)
#pragma unroll
            for (int ni = 0; ni < 4; ni++)
                wmma::load_matrix_sync(b[ni], sBlo + (wn * 64 + ni * 16) * LPAD + ks, LPAD);
#pragma unroll
            for (int ni = 0; ni < 4; ni++) {
                wmma::mma_sync(acc[0][ni], a0, b[ni], acc[0][ni]);
                wmma::mma_sync(acc[1][ni], a1, b[ni], acc[1][ni]);
            }
            // term 3: lo * hi
            wmma::load_matrix_sync(a0, sAlo + (wm * 32 +  0) * LPAD + ks, LPAD);
            wmma::load_matrix_sync(a1, sAlo + (wm * 32 + 16) * LPAD + ks, LPAD);
#pragma unroll
            for (int ni = 0; ni < 4; ni++)
                wmma::load_matrix_sync(b[ni], sBhi + (wn * 64 + ni * 16) * LPAD + ks, LPAD);
#pragma unroll
            for (int ni = 0; ni < 4; ni++) {
                wmma::mma_sync(acc[0][ni], a0, b[ni], acc[0][ni]);
                wmma::mma_sync(acc[1][ni], a1, b[ni], acc[1][ni]);
            }
        }
    }

    // Store: g_proj is padded to MPAD rows, no bounds checks needed.
#pragma unroll
    for (int mi = 0; mi < 2; mi++) {
        int row0 = bm + wm * 32 + mi * 16;
#pragma unroll
        for (int ni = 0; ni < 4; ni++) {
            float* cptr = g_proj + (size_t)row0 * PROJW + bn + wn * 64 + ni * 16;
            wmma::store_matrix_sync(cptr, acc[mi][ni], PROJW, wmma::mem_row_major);
        }
    }
}

// ---------------------------------------------------------------------------
// Edge phase: scores + softmax + aggregate + residual, NPB nodes per block.
// neighbor_indices / affinity_bins are int32 on device (JAX x64 off).
// ---------------------------------------------------------------------------
#define NPB 4

__global__ __launch_bounds__(256) void edge_kernel(
    const float* __restrict__ z, const int* __restrict__ nbr,
    const int* __restrict__ bins, const float* __restrict__ y_w,
    const float* __restrict__ c_bins, const float* __restrict__ rw,
    float* __restrict__ out, int N)
{
    __shared__ float s_y[NHEADS * HDIM];      // 16 KB
    __shared__ float s_S[HDIM];               // 2 KB
    __shared__ float s_sc[KNBR * NHEADS];     // scores -> attn
    __shared__ int   s_idx[KNBR];
    __shared__ int   s_bin[KNBR];
    __shared__ float s_cb[NBINS * NHEADS];
    __shared__ int   s_anyvalid;

    const int tid  = threadIdx.x;
    const int lane = tid & 31;
    const int warp = tid >> 5;

    for (int i = tid; i < NHEADS * HDIM; i += 256) s_y[i] = y_w[i];
    if (tid < NBINS * NHEADS) s_cb[tid] = c_bins[tid];
    const float rweight = rw[0];

    for (int ni = 0; ni < NPB; ni++) {
        const int node = blockIdx.x * NPB + ni;
        if (node >= N) break;   // uniform across block

        __syncthreads();        // guards smem reuse + initial y/cb loads
        s_S[tid]       = g_proj[(size_t)node * PROJW + tid];
        s_S[tid + 256] = g_proj[(size_t)node * PROJW + tid + 256];
        if (warp == 0) {
            int m = nbr[(size_t)node * KNBR + lane];
            s_idx[lane] = m;
            s_bin[lane] = bins[(size_t)node * KNBR + lane];
            unsigned bal = __ballot_sync(0xffffffffu, m >= 0);
            if (lane == 0) s_anyvalid = (bal != 0u);
        }
        __syncthreads();

        if (!s_anyvalid) {
            out[(size_t)node * HDIM + tid]       = z[(size_t)node * HDIM + tid];
            out[(size_t)node * HDIM + tid + 256] = z[(size_t)node * HDIM + tid + 256];
            continue;
        }

        // ---- scores: warp w handles k = w, w+8, ... ----
        const float4* s4 = (const float4*)s_S;
        const float4* y4 = (const float4*)s_y;
        for (int k = warp; k < KNBR; k += 8) {
            const int m = s_idx[k];
            float acc[NHEADS];
#pragma unroll
            for (int e = 0; e < NHEADS; e++) acc[e] = 0.0f;
            if (m >= 0) {
                const float4* prow = (const float4*)(g_proj + (size_t)m * PROJW + 512);
#pragma unroll
                for (int i = 0; i < 4; i++) {
                    const int dv = i * 32 + lane;
                    float4 p = prow[dv];
                    float4 s = s4[dv];
                    float h0 = lrelu(p.x + s.x);
                    float h1 = lrelu(p.y + s.y);
                    float h2 = lrelu(p.z + s.z);
                    float h3 = lrelu(p.w + s.w);
#pragma unroll
                    for (int e = 0; e < NHEADS; e++) {
                        float4 yv = y4[e * 128 + dv];
                        acc[e] += yv.x * h0 + yv.y * h1 + yv.z * h2 + yv.w * h3;
                    }
                }
            }
#pragma unroll
            for (int e = 0; e < NHEADS; e++) {
                float v = acc[e];
                v += __shfl_down_sync(0xffffffffu, v, 16);
                v += __shfl_down_sync(0xffffffffu, v, 8);
                v += __shfl_down_sync(0xffffffffu, v, 4);
                v += __shfl_down_sync(0xffffffffu, v, 2);
                v += __shfl_down_sync(0xffffffffu, v, 1);
                if (lane == 0)
                    s_sc[k * NHEADS + e] =
                        (m >= 0) ? (v + s_cb[s_bin[k] * NHEADS + e]) : -1.0e9f;
            }
        }
        __syncthreads();

        // ---- softmax over k, per head (8 threads) ----
        if (tid < NHEADS) {
            float mx = -3.0e38f;
#pragma unroll
            for (int k = 0; k < KNBR; k++) mx = fmaxf(mx, s_sc[k * NHEADS + tid]);
            float sum = 0.0f;
#pragma unroll
            for (int k = 0; k < KNBR; k++) sum += expf(s_sc[k * NHEADS + tid] - mx);
            float inv = 1.0f / sum;
#pragma unroll
            for (int k = 0; k < KNBR; k++)
                s_sc[k * NHEADS + tid] = expf(s_sc[k * NHEADS + tid] - mx) * inv;
        }
        __syncthreads();

        // ---- aggregate + residual: thread owns d = tid and tid+256 ----
        const int d0 = tid, d1 = tid + 256;
        const int e0 = d0 >> 6, e1 = d1 >> 6;
        float acc0 = 0.0f, acc1 = 0.0f;
#pragma unroll 4
        for (int k = 0; k < KNBR; k++) {
            const int m = s_idx[k];
            if (m < 0) continue;   // attn is exactly 0 for invalid edges
            const float* wrow = g_proj + (size_t)m * PROJW + 1024;
            acc0 += s_sc[k * NHEADS + e0] * wrow[d0];
            acc1 += s_sc[k * NHEADS + e1] * wrow[d1];
        }
        const float z0 = z[(size_t)node * HDIM + d0];
        const float z1 = z[(size_t)node * HDIM + d1];
        out[(size_t)node * HDIM + d0] = lrelu(acc0 + rweight * z0);
        out[(size_t)node * HDIM + d1] = lrelu(acc1 + rweight * z1);
    }
}

// ---------------------------------------------------------------------------
extern "C" void kernel_launch(void* const* d_in, const int* in_sizes, int n_in,
                              void* d_out, int out_size) {
    const float* z      = (const float*)d_in[0];
    // d_in[1] (A) is all zeros and unused by the reference — skipped.
    const int*   nbr    = (const int*)d_in[2];
    const int*   bins   = (const int*)d_in[3];
    const float* P_w    = (const float*)d_in[4];
    const float* y_w    = (const float*)d_in[5];
    const float* W_w    = (const float*)d_in[6];
    const float* c_bins = (const float*)d_in[7];
    const float* rw     = (const float*)d_in[8];
    float*       out    = (float*)d_out;

    const int N      = in_sizes[0] / HDIM;
    const int mtiles = (N + 127) / 128;
    const int Mp     = mtiles * 128;

    cudaFuncSetAttribute(gemm_wmma_kernel,
                         cudaFuncAttributeMaxDynamicSharedMemorySize, GEMM_SMEM);

    conv_a_kernel<<<(Mp * HDIM + 255) / 256, 256>>>(z, N, Mp);
    conv_b_kernel<<<(PROJW * HDIM + 255) / 256, 256>>>(P_w, W_w);

    dim3 g(PROJW / 128, mtiles);
    gemm_wmma_kernel<<<g, 256, GEMM_SMEM>>>(N);

    edge_kernel<<<(N + NPB - 1) / NPB, 256>>>(z, nbr, bins, y_w, c_bins, rw, out, N);
}

// round 8
// speedup vs baseline: 1.3562x; 1.0156x over previous
#include <cuda_runtime.h>
#include <cuda_bf16.h>
#include <mma.h>
#include <cstdint>

using namespace nvcuda;

#define HDIM  512
#define KNBR  32
#define NHEADS 8
#define NBINS 10
#define NMAX  10000
#define MPAD  10112      // ceil(10000/128)*128
#define NEG_SLOPE 0.2f
#define PROJW 1536       // [S | Pn | Wt]

__device__ float g_proj[(size_t)MPAD * PROJW];          // per-node projections (fp32)
__device__ __nv_bfloat16 g_Ahi[(size_t)MPAD * HDIM];
__device__ __nv_bfloat16 g_Alo[(size_t)MPAD * HDIM];
__device__ __nv_bfloat16 g_Bhi[(size_t)PROJW * HDIM];
__device__ __nv_bfloat16 g_Blo[(size_t)PROJW * HDIM];

__device__ __forceinline__ float lrelu(float x) {
    return x >= 0.0f ? x : NEG_SLOPE * x;
}

// ===========================================================================
// Conversions: fp32 -> (hi, lo) bf16 split
// ===========================================================================
__global__ void conv_a_kernel(const float* __restrict__ z, int M, int Mp) {
    int i = blockIdx.x * blockDim.x + threadIdx.x;
    if (i >= Mp * HDIM) return;
    int row = i >> 9;
    float x = (row < M) ? z[i] : 0.0f;
    __nv_bfloat16 h = __float2bfloat16(x);
    g_Ahi[i] = h;
    g_Alo[i] = __float2bfloat16(x - __bfloat162float(h));
}

__global__ void conv_b_kernel(const float* __restrict__ P_w, const float* __restrict__ W_w) {
    int i = blockIdx.x * blockDim.x + threadIdx.x;
    if (i >= PROJW * HDIM) return;
    int j = i >> 9;
    int hcol = i & (HDIM - 1);
    float x;
    if (j < 512)        x = P_w[(size_t)j * 1024 + hcol];
    else if (j < 1024)  x = P_w[(size_t)(j - 512) * 1024 + 512 + hcol];
    else                x = W_w[(size_t)(j - 1024) * 512 + hcol];
    __nv_bfloat16 h = __float2bfloat16(x);
    g_Bhi[i] = h;
    g_Blo[i] = __float2bfloat16(x - __bfloat162float(h));
}

// ===========================================================================
// wmma bf16 3-term GEMM: C[m,j] = sum_h A[m,h]*B[j,h]  (fp32 accumulate)
// CTA tile 128x128, 8 warps (4m x 2n), warp tile 32x64 (2x4 wmma frags).
// K chunked by 32: 4 smem tiles of 128 x 48(padded) bf16 = 48 KB.
// ===========================================================================
#define KC 32
#define LPAD 48   // padded row length in elements; 96 B row stride (16B-aligned)
#define TILE_ELEMS (128 * LPAD)
#define GEMM_SMEM (4 * TILE_ELEMS * 2)

__global__ __launch_bounds__(256) void gemm_wmma_kernel(int M) {
    extern __shared__ __nv_bfloat16 sm[];
    __nv_bfloat16* sAhi = sm;
    __nv_bfloat16* sAlo = sm + TILE_ELEMS;
    __nv_bfloat16* sBhi = sm + 2 * TILE_ELEMS;
    __nv_bfloat16* sBlo = sm + 3 * TILE_ELEMS;

    const int tid = threadIdx.x;
    const int wid = tid >> 5;
    const int bm = blockIdx.y * 128;
    const int bn = blockIdx.x * 128;
    const int wm = wid & 3;    // 0..3 -> m offset wm*32
    const int wn = wid >> 2;   // 0..1 -> n offset wn*64

    wmma::fragment<wmma::accumulator, 16, 16, 16, float> acc[2][4];
#pragma unroll
    for (int i = 0; i < 2; i++)
#pragma unroll
        for (int j = 0; j < 4; j++) wmma::fill_fragment(acc[i][j], 0.0f);

    const __nv_bfloat16* gsrc[4];
    gsrc[0] = g_Ahi + (size_t)bm * HDIM;
    gsrc[1] = g_Alo + (size_t)bm * HDIM;
    gsrc[2] = g_Bhi + (size_t)bn * HDIM;
    gsrc[3] = g_Blo + (size_t)bn * HDIM;
    __nv_bfloat16* sdst[4] = { sAhi, sAlo, sBhi, sBlo };

    for (int k0 = 0; k0 < HDIM; k0 += KC) {
        __syncthreads();   // protect previous iteration's reads
        // Each tile: 128 rows x 32 bf16 (64 B) = 512 uint4 vectors.
#pragma unroll
        for (int t = 0; t < 4; t++) {
            const __nv_bfloat16* src = gsrc[t] + k0;
            __nv_bfloat16* dst = sdst[t];
#pragma unroll
            for (int it = 0; it < 2; it++) {
                int v = tid + it * 256;       // 0..511
                int row = v >> 2;
                int c = v & 3;                // 8-element (16B) vector index
                uint4 val = *(const uint4*)(src + (size_t)row * HDIM + c * 8);
                *(uint4*)(dst + row * LPAD + c * 8) = val;
            }
        }
        __syncthreads();

#pragma unroll
        for (int ks = 0; ks < KC; ks += 16) {
            wmma::fragment<wmma::matrix_a, 16, 16, 16, __nv_bfloat16, wmma::row_major> a0, a1;
            wmma::fragment<wmma::matrix_b, 16, 16, 16, __nv_bfloat16, wmma::col_major> b[4];

            // term 1: hi * hi
            wmma::load_matrix_sync(a0, sAhi + (wm * 32 +  0) * LPAD + ks, LPAD);
            wmma::load_matrix_sync(a1, sAhi + (wm * 32 + 16) * LPAD + ks, LPAD);
#pragma unroll
            for (int ni = 0; ni < 4; ni++)
                wmma::load_matrix_sync(b[ni], sBhi + (wn * 64 + ni * 16) * LPAD + ks, LPAD);
#pragma unroll
            for (int ni = 0; ni < 4; ni++) {
                wmma::mma_sync(acc[0][ni], a0, b[ni], acc[0][ni]);
                wmma::mma_sync(acc[1][ni], a1, b[ni], acc[1][ni]);
            }
            // term 2: hi * lo  (a still hi)
#pragma unroll
            for (int ni = 0; ni < 4; ni++)
                wmma::load_matrix_sync(b[ni], sBlo + (wn * 64 + ni * 16) * LPAD + ks, LPAD);
#pragma unroll
            for (int ni = 0; ni < 4; ni++) {
                wmma::mma_sync(acc[0][ni], a0, b[ni], acc[0][ni]);
                wmma::mma_sync(acc[1][ni], a1, b[ni], acc[1][ni]);
            }
            // term 3: lo * hi
            wmma::load_matrix_sync(a0, sAlo + (wm * 32 +  0) * LPAD + ks, LPAD);
            wmma::load_matrix_sync(a1, sAlo + (wm * 32 + 16) * LPAD + ks, LPAD);
#pragma unroll
            for (int ni = 0; ni < 4; ni++)
                wmma::load_matrix_sync(b[ni], sBhi + (wn * 64 + ni * 16) * LPAD + ks, LPAD);
#pragma unroll
            for (int ni = 0; ni < 4; ni++) {
                wmma::mma_sync(acc[0][ni], a0, b[ni], acc[0][ni]);
                wmma::mma_sync(acc[1][ni], a1, b[ni], acc[1][ni]);
            }
        }
    }

    // Store: g_proj is padded to MPAD rows, no bounds checks needed.
#pragma unroll
    for (int mi = 0; mi < 2; mi++) {
        int row0 = bm + wm * 32 + mi * 16;
#pragma unroll
        for (int ni = 0; ni < 4; ni++) {
            float* cptr = g_proj + (size_t)row0 * PROJW + bn + wn * 64 + ni * 16;
            wmma::store_matrix_sync(cptr, acc[mi][ni], PROJW, wmma::mem_row_major);
        }
    }
}

// ---------------------------------------------------------------------------
// Edge phase v2: y register-resident (zero per-edge y LDS traffic).
// Scores: 2 k per pass, 4 quarter-warps per k; lane owns float4 chunk dv.
// neighbor_indices / affinity_bins are int32 on device (JAX x64 off).
// ---------------------------------------------------------------------------
#define NPB 4

__global__ __launch_bounds__(256) void edge_kernel(
    const float* __restrict__ z, const int* __restrict__ nbr,
    const int* __restrict__ bins, const float* __restrict__ y_w,
    const float* __restrict__ c_bins, const float* __restrict__ rw,
    float* __restrict__ out, int N)
{
    __shared__ float s_part[KNBR][NHEADS][4];   // per-quarter partial scores, 4 KB
    __shared__ float s_attn[KNBR * NHEADS];     // softmax result, 1 KB
    __shared__ int   s_idx[KNBR];
    __shared__ int   s_bin[KNBR];
    __shared__ float s_cb[NBINS * NHEADS];
    __shared__ int   s_anyvalid;

    const int tid  = threadIdx.x;
    const int lane = tid & 31;
    const int warp = tid >> 5;
    const int q    = warp & 3;          // quarter of the d-range
    const int kl   = warp >> 2;         // 0/1: k offset within pass
    const int dv   = q * 32 + lane;     // float4 chunk index in [0,128)

    // y register-resident: 8 heads x one float4 chunk per lane (loaded once).
    float4 yreg[NHEADS];
    const float4* y4 = (const float4*)y_w;
#pragma unroll
    for (int e = 0; e < NHEADS; e++) yreg[e] = y4[e * 128 + dv];

    if (tid < NBINS * NHEADS) s_cb[tid] = c_bins[tid];
    const float rweight = rw[0];

    for (int ni = 0; ni < NPB; ni++) {
        const int node = blockIdx.x * NPB + ni;
        if (node >= N) break;   // uniform across block

        __syncthreads();        // protect smem reuse across nodes (and cb load)
        if (warp == 0) {
            int m = nbr[(size_t)node * KNBR + lane];
            s_idx[lane] = m;
            s_bin[lane] = bins[(size_t)node * KNBR + lane];
            unsigned bal = __ballot_sync(0xffffffffu, m >= 0);
            if (lane == 0) s_anyvalid = (bal != 0u);
        }
        // self projection chunk, register-cached for the whole node
        const float4 sreg = ((const float4*)(g_proj + (size_t)node * PROJW))[dv];
        __syncthreads();

        if (!s_anyvalid) {
            out[(size_t)node * HDIM + tid]       = z[(size_t)node * HDIM + tid];
            out[(size_t)node * HDIM + tid + 256] = z[(size_t)node * HDIM + tid + 256];
            continue;
        }

        // ---- scores: only memory op per k is one gathered float4 of Pn ----
#pragma unroll
        for (int pass = 0; pass < KNBR / 2; pass++) {
            const int k = pass * 2 + kl;
            const int m = s_idx[k];
            if (m >= 0) {
                float4 p = ((const float4*)(g_proj + (size_t)m * PROJW + 512))[dv];
                const float h0 = lrelu(p.x + sreg.x);
                const float h1 = lrelu(p.y + sreg.y);
                const float h2 = lrelu(p.z + sreg.z);
                const float h3 = lrelu(p.w + sreg.w);
                float acc[NHEADS];
#pragma unroll
                for (int e = 0; e < NHEADS; e++)
                    acc[e] = yreg[e].x * h0 + yreg[e].y * h1
                           + yreg[e].z * h2 + yreg[e].w * h3;
#pragma unroll
                for (int e = 0; e < NHEADS; e++) {
                    float v = acc[e];
                    v += __shfl_down_sync(0xffffffffu, v, 16);
                    v += __shfl_down_sync(0xffffffffu, v, 8);
                    v += __shfl_down_sync(0xffffffffu, v, 4);
                    v += __shfl_down_sync(0xffffffffu, v, 2);
                    v += __shfl_down_sync(0xffffffffu, v, 1);
                    if (lane == 0) s_part[k][e][q] = v;
                }
            }
        }
        __syncthreads();

        // ---- softmax over k, per head (8 threads; partials summed here) ----
        if (tid < NHEADS) {
            const int e = tid;
            float sc[KNBR];
            float mx = -3.0e38f;
#pragma unroll
            for (int k = 0; k < KNBR; k++) {
                float v;
                if (s_idx[k] < 0) {
                    v = -1.0e9f;
                } else {
                    v = s_part[k][e][0] + s_part[k][e][1]
                      + s_part[k][e][2] + s_part[k][e][3]
                      + s_cb[s_bin[k] * NHEADS + e];
                }
                sc[k] = v;
                mx = fmaxf(mx, v);
            }
            float sum = 0.0f;
#pragma unroll
            for (int k = 0; k < KNBR; k++) {
                sc[k] = expf(sc[k] - mx);
                sum += sc[k];
            }
            const float inv = 1.0f / sum;
#pragma unroll
            for (int k = 0; k < KNBR; k++)
                s_attn[k * NHEADS + e] = sc[k] * inv;
        }
        __syncthreads();

        // ---- aggregate + residual: thread owns d = tid and tid+256 ----
        const int d0 = tid, d1 = tid + 256;
        const int e0 = d0 >> 6, e1 = d1 >> 6;
        float acc0 = 0.0f, acc1 = 0.0f;
#pragma unroll 4
        for (int k = 0; k < KNBR; k++) {
            const int m = s_idx[k];
            if (m < 0) continue;   // attn is exactly 0 for invalid edges
            const float* wrow = g_proj + (size_t)m * PROJW + 1024;
            acc0 += s_attn[k * NHEADS + e0] * wrow[d0];
            acc1 += s_attn[k * NHEADS + e1] * wrow[d1];
        }
        const float z0 = z[(size_t)node * HDIM + d0];
        const float z1 = z[(size_t)node * HDIM + d1];
        out[(size_t)node * HDIM + d0] = lrelu(acc0 + rweight * z0);
        out[(size_t)node * HDIM + d1] = lrelu(acc1 + rweight * z1);
    }
}

// ---------------------------------------------------------------------------
extern "C" void kernel_launch(void* const* d_in, const int* in_sizes, int n_in,
                              void* d_out, int out_size) {
    const float* z      = (const float*)d_in[0];
    // d_in[1] (A) is all zeros and unused by the reference — skipped.
    const int*   nbr    = (const int*)d_in[2];
    const int*   bins   = (const int*)d_in[3];
    const float* P_w    = (const float*)d_in[4];
    const float* y_w    = (const float*)d_in[5];
    const float* W_w    = (const float*)d_in[6];
    const float* c_bins = (const float*)d_in[7];
    const float* rw     = (const float*)d_in[8];
    float*       out    = (float*)d_out;

    const int N      = in_sizes[0] / HDIM;
    const int mtiles = (N + 127) / 128;
    const int Mp     = mtiles * 128;

    cudaFuncSetAttribute(gemm_wmma_kernel,
                         cudaFuncAttributeMaxDynamicSharedMemorySize, GEMM_SMEM);

    conv_a_kernel<<<(Mp * HDIM + 255) / 256, 256>>>(z, N, Mp);
    conv_b_kernel<<<(PROJW * HDIM + 255) / 256, 256>>>(P_w, W_w);

    dim3 g(PROJW / 128, mtiles);
    gemm_wmma_kernel<<<g, 256, GEMM_SMEM>>>(N);

    edge_kernel<<<(N + NPB - 1) / NPB, 256>>>(z, nbr, bins, y_w, c_bins, rw, out, N);
}